// round 16
// baseline (speedup 1.0000x reference)
#include <cuda_runtime.h>
#include <cuda_fp16.h>
#include <math.h>
#include <stdint.h>

// Problem dims
#define TSLICES 10
#define NTOPICS 50
#define M_ROWS  500
#define M_PAD   512
#define N_COLS  50000
#define N_PAD   50048          // 391 strips of 128
#define K_DIM   1024
#define BATCH   256

#define NSTRIP  391
#define CTA_M   256
#define CTA_N   128
#define KSTEP   64
#define NSTAGE  (K_DIM / KSTEP)   // 16
#define NPART   (2 * NSTRIP)      // 782 parts of 64 cols per row

// ---------------------------------------------------------------------------
// Scratch (device globals).  g_eh holds fp16 exp(L - mloc[row,part]).
// ---------------------------------------------------------------------------
__device__ __half g_eh[(size_t)M_ROWS * N_COLS];             // 50 MB
__device__ float g_rowmax[M_ROWS];
__device__ float g_rowsum[M_ROWS];
__device__ float g_c[BATCH * NTOPICS];
__device__ int   g_tidx[BATCH];
__device__ int   g_order[BATCH];                             // batches sorted by t
__device__ float g_pmax[(size_t)M_PAD * NPART];
__device__ float g_psum[(size_t)M_PAD * NPART];
__device__ int   g_wflag[NSTRIP * 2];                        // per (strip, half)

__device__ __align__(16) __half g_Wh[(size_t)N_PAD * K_DIM]; // 102.5 MB
__device__ __align__(16) __half g_Wl[(size_t)N_PAD * K_DIM]; // 102.5 MB
__device__ __align__(16) __half g_Eh[(size_t)M_PAD * K_DIM]; // 1 MB
__device__ __align__(16) __half g_El[(size_t)M_PAD * K_DIM]; // 1 MB

// ---------------------------------------------------------------------------
// PTX helpers (base-target sm_80/90 instructions only)
// ---------------------------------------------------------------------------
__device__ __forceinline__ uint32_t s2u(const void* p) {
    uint32_t a;
    asm("{ .reg .u64 t; cvta.to.shared.u64 t, %1; cvt.u32.u64 %0, t; }" : "=r"(a) : "l"(p));
    return a;
}
__device__ __forceinline__ void cpasync16(uint32_t saddr, const void* gaddr) {
    asm volatile("cp.async.cg.shared.global [%0], [%1], 16;" :: "r"(saddr), "l"(gaddr) : "memory");
}
#define CP_COMMIT() asm volatile("cp.async.commit_group;" ::: "memory")
#define CP_WAIT(n)  asm volatile("cp.async.wait_group %0;" :: "n"(n) : "memory")

__device__ __forceinline__ void ldsm_x4(uint32_t* r, uint32_t a) {
    asm volatile("ldmatrix.sync.aligned.m8n8.x4.shared.b16 {%0,%1,%2,%3}, [%4];"
                 : "=r"(r[0]), "=r"(r[1]), "=r"(r[2]), "=r"(r[3]) : "r"(a));
}
__device__ __forceinline__ void mma16816(float* c, const uint32_t* a, const uint32_t* b) {
    asm volatile("mma.sync.aligned.m16n8k16.row.col.f32.f16.f16.f32 "
                 "{%0,%1,%2,%3}, {%4,%5,%6,%7}, {%8,%9}, {%0,%1,%2,%3};"
                 : "+f"(c[0]), "+f"(c[1]), "+f"(c[2]), "+f"(c[3])
                 : "r"(a[0]), "r"(a[1]), "r"(a[2]), "r"(a[3]), "r"(b[0]), "r"(b[1]));
}
#define SWZ(o) ((o) ^ (((o) >> 3) & 0x70))

// ---------------------------------------------------------------------------
// k0: normalize time_index + counting sort + zero W-conversion flags
// ---------------------------------------------------------------------------
__global__ void k0_index(const int* __restrict__ tix_words) {
    __shared__ int s_nonzero;
    __shared__ int tval[BATCH];
    int t = threadIdx.x;
    for (int i = t; i < NSTRIP * 2; i += 256) g_wflag[i] = 0;
    if (t == 0) s_nonzero = 0;
    __syncthreads();
    if ((t & 1) && tix_words[t] != 0) atomicOr(&s_nonzero, 1);
    __syncthreads();
    int v = (s_nonzero == 0) ? tix_words[2 * t] : tix_words[t];
    g_tidx[t] = v;
    tval[t] = v;
    __syncthreads();
    if (t == 0) {
        int cnt[TSLICES], off[TSLICES];
        #pragma unroll
        for (int s = 0; s < TSLICES; s++) cnt[s] = 0;
        for (int i = 0; i < BATCH; i++) cnt[tval[i]]++;
        int a = 0;
        #pragma unroll
        for (int s = 0; s < TSLICES; s++) { off[s] = a; a += cnt[s]; }
        for (int i = 0; i < BATCH; i++) g_order[off[tval[i]]++] = i;
    }
}

// ---------------------------------------------------------------------------
// fp16 hi/lo split helpers
// ---------------------------------------------------------------------------
__device__ __forceinline__ void split8(const float* x, uint32_t* hw, uint32_t* lw) {
    #pragma unroll
    for (int i = 0; i < 4; i++) {
        __half h0 = __float2half_rn(x[2*i]);
        __half l0 = __float2half_rn(x[2*i]   - __half2float(h0));
        __half h1 = __float2half_rn(x[2*i+1]);
        __half l1 = __float2half_rn(x[2*i+1] - __half2float(h1));
        hw[i] = (uint32_t)__half_as_ushort(h0) | ((uint32_t)__half_as_ushort(h1) << 16);
        lw[i] = (uint32_t)__half_as_ushort(l0) | ((uint32_t)__half_as_ushort(l1) << 16);
    }
}

// prepE: E fp32 [500][1024] -> g_Eh/g_El half [512][1024] (rows >= 500 zero)
__global__ __launch_bounds__(256) void prepE(const float* __restrict__ E) {
    int idx = blockIdx.x * 256 + threadIdx.x;
    int r = idx >> 7, g = idx & 127;
    float x[8];
    if (r < M_ROWS) {
        const float4* p = (const float4*)(E + (size_t)r * K_DIM + g * 8);
        float4 a = p[0], b = p[1];
        x[0]=a.x; x[1]=a.y; x[2]=a.z; x[3]=a.w; x[4]=b.x; x[5]=b.y; x[6]=b.z; x[7]=b.w;
    } else {
        #pragma unroll
        for (int i = 0; i < 8; i++) x[i] = 0.0f;
    }
    uint32_t hw[4], lw[4];
    split8(x, hw, lw);
    size_t d = ((size_t)r * K_DIM + g * 8) >> 3;
    ((uint4*)g_Eh)[d] = make_uint4(hw[0], hw[1], hw[2], hw[3]);
    ((uint4*)g_El)[d] = make_uint4(lw[0], lw[1], lw[2], lw[3]);
}

// ---------------------------------------------------------------------------
// kgemm: HMMA GEMM, fp16 hi/lo 3-product split — R9/R12 mainloop verbatim.
// NEW prologue: the two CTAs of each strip cooperatively convert the strip's
// W fp32 -> g_Wh/g_Wl (half each, 256KB r/w ~4us), flag-handshake, then run.
// This deletes the standalone prepW (~90-140us serial); the conversion DRAM
// traffic overlaps the tensor-bound mainloop (DRAM was at 8%).
// Epilogue: per-(row, 64col part) local max, fp16 exp store, partial sums.
// Smem/stage: Ah 32K | Al 32K | Bh 16K | Bl 16K = 96K; x2 stages = 192K.
// ---------------------------------------------------------------------------
#define ST_STRIDE 98304
#define AH_OFF 0
#define AL_OFF 32768
#define BH_OFF 65536
#define BL_OFF 81920
#define GEMM_SMEM (2 * ST_STRIDE)

__device__ __forceinline__ void issueA(uint32_t sb, int buf, int s, int m0, int tid) {
    const int k0 = s * KSTEP;
    uint32_t base = sb + buf * ST_STRIDE;
    #pragma unroll
    for (int i = 0; i < 8; i++) {
        int cid = tid + i * 256;
        int row = cid >> 3, c = cid & 7;
        uint32_t sw = SWZ((uint32_t)(row * 128 + c * 16));
        cpasync16(base + AH_OFF + sw, g_Eh + (size_t)(m0 + row) * K_DIM + k0 + c * 8);
        cpasync16(base + AL_OFF + sw, g_El + (size_t)(m0 + row) * K_DIM + k0 + c * 8);
    }
}
__device__ __forceinline__ void issueB(uint32_t sb, int buf, int s, int n0, int tid) {
    const int k0 = s * KSTEP;
    uint32_t base = sb + buf * ST_STRIDE;
    #pragma unroll
    for (int i = 0; i < 4; i++) {
        int cid = tid + i * 256;
        int row = cid >> 3, c = cid & 7;
        uint32_t sw = SWZ((uint32_t)(row * 128 + c * 16));
        cpasync16(base + BH_OFF + sw, g_Wh + (size_t)(n0 + row) * K_DIM + k0 + c * 8);
        cpasync16(base + BL_OFF + sw, g_Wl + (size_t)(n0 + row) * K_DIM + k0 + c * 8);
    }
}

__global__ __launch_bounds__(256, 1) void kgemm(const float* __restrict__ W) {
    extern __shared__ char smem[];
    const uint32_t sb = s2u(smem);
    const int tid  = threadIdx.x;
    const int lane = tid & 31;
    const int wid  = tid >> 5;
    const int wm   = (wid >> 1) * 64;   // warp M offset: 0,64,128,192
    const int wn   = (wid & 1) * 64;    // warp N offset: 0,64
    const int half = blockIdx.x;           // doubles as M-tile index
    const int m0   = half * CTA_M;         // x fast -> B L2 reuse across M-tiles
    const int strip = blockIdx.y;
    const int n0   = strip * CTA_N;

    // ---- Prologue: convert my half of this strip's W (64 rows x 1024) ----
    {
        const int baseRow = n0 + half * 64;
        for (int tsk = tid; tsk < 64 * 128; tsk += 256) {
            int row = tsk >> 7;
            int gc  = (tsk & 127) * 8;
            int v = baseRow + row;
            float x[8];
            if (v < N_COLS) {
                const float4* p = (const float4*)(W + (size_t)v * K_DIM + gc);
                float4 a = p[0], b = p[1];
                x[0]=a.x; x[1]=a.y; x[2]=a.z; x[3]=a.w;
                x[4]=b.x; x[5]=b.y; x[6]=b.z; x[7]=b.w;
            } else {
                #pragma unroll
                for (int i = 0; i < 8; i++) x[i] = 0.0f;
            }
            uint32_t hw[4], lw[4];
            split8(x, hw, lw);
            size_t d = ((size_t)v * K_DIM + gc) >> 3;
            ((uint4*)g_Wh)[d] = make_uint4(hw[0], hw[1], hw[2], hw[3]);
            ((uint4*)g_Wl)[d] = make_uint4(lw[0], lw[1], lw[2], lw[3]);
        }
        __threadfence();
        __syncthreads();
        if (tid == 0) atomicExch(&g_wflag[strip * 2 + half], 1);
    }

    float acc[4][8][4];
    #pragma unroll
    for (int i = 0; i < 4; i++)
        #pragma unroll
        for (int j = 0; j < 8; j++)
            #pragma unroll
            for (int q = 0; q < 4; q++) acc[i][j][q] = 0.0f;

    // A ldsm_x4 (16x16): lanes 0-15 -> rows, lanes 16-31 -> +16B col
    const int arow = wm + (lane & 15);
    const int acol = (lane >> 4) << 4;
    // B paired ldsm_x4 loads fragments (2jp, 2jp+1)
    const int brow = wn + (lane & 7) + ((lane >> 4) << 3);
    const int bcol = ((lane >> 3) & 1) << 4;

    // A of stage 0 is independent of W -> issue before spinning
    issueA(sb, 0, 0, m0, tid);

    // wait for partner's half
    if (tid == 0) {
        while (atomicAdd(&g_wflag[strip * 2 + (half ^ 1)], 0) == 0) { }
    }
    __syncthreads();
    __threadfence();

    issueB(sb, 0, 0, n0, tid);
    CP_COMMIT();

    for (int s = 0; s < NSTAGE; s++) {
        const int buf = s & 1;
        if (s + 1 < NSTAGE) {
            issueA(sb, buf ^ 1, s + 1, m0, tid);
            issueB(sb, buf ^ 1, s + 1, n0, tid);
            CP_COMMIT();
            CP_WAIT(1);
        } else {
            CP_WAIT(0);
        }
        __syncthreads();

        const uint32_t tb = sb + buf * ST_STRIDE;
        #pragma unroll
        for (int kk = 0; kk < 4; kk++) {
            const int kb = kk * 32;
            uint32_t ah[4][4], al[4][4], bh[4][4], bl[4][4];
            #pragma unroll
            for (int i = 0; i < 4; i++) {
                uint32_t off = (uint32_t)((arow + i * 16) * 128 + kb + acol);
                ldsm_x4(ah[i], tb + AH_OFF + SWZ(off));
            }
            #pragma unroll
            for (int jp = 0; jp < 4; jp++) {
                uint32_t off = (uint32_t)((brow + jp * 16) * 128 + kb + bcol);
                ldsm_x4(bh[jp], tb + BH_OFF + SWZ(off));
            }
            #pragma unroll
            for (int i = 0; i < 4; i++) {
                uint32_t off = (uint32_t)((arow + i * 16) * 128 + kb + acol);
                ldsm_x4(al[i], tb + AL_OFF + SWZ(off));
            }
            #pragma unroll
            for (int jp = 0; jp < 4; jp++) {
                uint32_t off = (uint32_t)((brow + jp * 16) * 128 + kb + bcol);
                ldsm_x4(bl[jp], tb + BL_OFF + SWZ(off));
            }
            #pragma unroll
            for (int i = 0; i < 4; i++)
                #pragma unroll
                for (int j = 0; j < 8; j++)
                    mma16816(acc[i][j], ah[i], &bh[j >> 1][(j & 1) * 2]);
            #pragma unroll
            for (int i = 0; i < 4; i++)
                #pragma unroll
                for (int j = 0; j < 8; j++)
                    mma16816(acc[i][j], al[i], &bh[j >> 1][(j & 1) * 2]);
            #pragma unroll
            for (int i = 0; i < 4; i++)
                #pragma unroll
                for (int j = 0; j < 8; j++)
                    mma16816(acc[i][j], ah[i], &bl[j >> 1][(j & 1) * 2]);
        }
        __syncthreads();
    }

    // ---- Epilogue: per-(row, part) local max, fp16 store, partial sums ----
    const int erow  = m0 + wm + (lane >> 2);
    const int ecol0 = n0 + wn + 2 * (lane & 3);
    const int part  = strip * 2 + (wn >> 6);
    #pragma unroll
    for (int i = 0; i < 4; i++) {
        float m0l = -1e30f, m1l = -1e30f;
        #pragma unroll
        for (int j = 0; j < 8; j++) {
            int cc = ecol0 + j * 8;
            if (cc < N_COLS) {
                m0l = fmaxf(m0l, fmaxf(acc[i][j][0], acc[i][j][1]));
                m1l = fmaxf(m1l, fmaxf(acc[i][j][2], acc[i][j][3]));
            }
        }
        m0l = fmaxf(m0l, __shfl_xor_sync(0xFFFFFFFF, m0l, 1));
        m0l = fmaxf(m0l, __shfl_xor_sync(0xFFFFFFFF, m0l, 2));
        m1l = fmaxf(m1l, __shfl_xor_sync(0xFFFFFFFF, m1l, 1));
        m1l = fmaxf(m1l, __shfl_xor_sync(0xFFFFFFFF, m1l, 2));

        float sl0 = 0.0f, sl1 = 0.0f;
        #pragma unroll
        for (int j = 0; j < 8; j++) {
            int cc = ecol0 + j * 8;
            if (cc >= N_COLS) continue;
            __half h0 = __float2half_rn(__expf(acc[i][j][0] - m0l));
            __half h1 = __float2half_rn(__expf(acc[i][j][1] - m0l));
            __half h2 = __float2half_rn(__expf(acc[i][j][2] - m1l));
            __half h3 = __float2half_rn(__expf(acc[i][j][3] - m1l));
            sl0 += __half2float(h0) + __half2float(h1);
            sl1 += __half2float(h2) + __half2float(h3);
            uint32_t p01 = (uint32_t)__half_as_ushort(h0) | ((uint32_t)__half_as_ushort(h1) << 16);
            uint32_t p23 = (uint32_t)__half_as_ushort(h2) | ((uint32_t)__half_as_ushort(h3) << 16);
            int r0 = erow + i * 16;
            if (r0 < M_ROWS)
                *(uint32_t*)(g_eh + (size_t)r0 * N_COLS + cc) = p01;
            int r1 = r0 + 8;
            if (r1 < M_ROWS)
                *(uint32_t*)(g_eh + (size_t)r1 * N_COLS + cc) = p23;
        }
        sl0 += __shfl_xor_sync(0xFFFFFFFF, sl0, 1);
        sl0 += __shfl_xor_sync(0xFFFFFFFF, sl0, 2);
        sl1 += __shfl_xor_sync(0xFFFFFFFF, sl1, 1);
        sl1 += __shfl_xor_sync(0xFFFFFFFF, sl1, 2);
        if ((lane & 3) == 0) {
            int row0 = erow + i * 16;
            g_pmax[(size_t)row0 * NPART + part] = m0l;
            g_psum[(size_t)row0 * NPART + part] = sl0;
            g_pmax[(size_t)(row0 + 8) * NPART + part] = m1l;
            g_psum[(size_t)(row0 + 8) * NPART + part] = sl1;
        }
    }
}

// ---------------------------------------------------------------------------
// k2r: merge NPART partials per row -> rowmax + rescaled rowsum
// ---------------------------------------------------------------------------
__global__ __launch_bounds__(256) void k2r() {
    const int r = blockIdx.x;
    const float* pm = g_pmax + (size_t)r * NPART;
    const float* ps = g_psum + (size_t)r * NPART;
    __shared__ float red[256];
    const int t = threadIdx.x;

    float m = -1e30f;
    for (int i = t; i < NPART; i += 256) m = fmaxf(m, pm[i]);
    red[t] = m;
    __syncthreads();
    for (int s = 128; s > 0; s >>= 1) {
        if (t < s) red[t] = fmaxf(red[t], red[t + s]);
        __syncthreads();
    }
    m = red[0];
    __syncthreads();

    float sum = 0.0f;
    for (int i = t; i < NPART; i += 256) sum += ps[i] * __expf(pm[i] - m);
    red[t] = sum;
    __syncthreads();
    for (int s = 128; s > 0; s >>= 1) {
        if (t < s) red[t] += red[t + s];
        __syncthreads();
    }
    if (t == 0) { g_rowmax[r] = m; g_rowsum[r] = red[0]; }
}

// ---------------------------------------------------------------------------
// k2b: c[b,k] = theta[b,k] / S[t_b*50+k]
// ---------------------------------------------------------------------------
__global__ void k2b_coeff(const float* __restrict__ theta) {
    int i = blockIdx.x * 256 + threadIdx.x;
    int b = i / NTOPICS, k = i - b * NTOPICS;
    g_c[i] = theta[i] / g_rowsum[g_tidx[b] * NTOPICS + k];
}

// ---------------------------------------------------------------------------
// k3: out[b,v] = sum_k c[b,k] * exp(L - M_r); stored fp16 values rescaled by
// sc[r] = exp(pm[r][part] - M_r) during smem staging. One 64-col part per
// block (782 blocks). Time-sorted batches -> lanes share t -> broadcast.
// ---------------------------------------------------------------------------
#define VT  64
#define EBS 66
#define K3_SMEM ((M_ROWS * EBS + M_ROWS) * 4)   // 134 KB

__global__ __launch_bounds__(256) void k3_out(float* __restrict__ out) {
    extern __shared__ float sm[];
    float* eb = sm;                   // [500][66]
    float* sc = sm + M_ROWS * EBS;    // [500] per-row rescale
    const int part = blockIdx.x;
    const int v0   = part * VT;
    const int tid  = threadIdx.x;

    for (int r = tid; r < M_ROWS; r += 256)
        sc[r] = __expf(g_pmax[(size_t)r * NPART + part] - g_rowmax[r]);
    __syncthreads();

    for (int i = tid; i < M_ROWS * 32; i += 256) {
        int r = i >> 5, p = i & 31;
        int vc = v0 + 2 * p;
        float x0 = 0.f, x1 = 0.f;
        if (vc + 1 < N_COLS) {
            uint32_t w = *(const uint32_t*)(g_eh + (size_t)r * N_COLS + vc);
            float f = sc[r];
            x0 = __half2float(__ushort_as_half((unsigned short)(w & 0xFFFF))) * f;
            x1 = __half2float(__ushort_as_half((unsigned short)(w >> 16))) * f;
        }
        eb[r * EBS + 2 * p]     = x0;
        eb[r * EBS + 2 * p + 1] = x1;
    }
    __syncthreads();

    const int b  = g_order[tid];
    const int rb = g_tidx[b] * NTOPICS;
    float creg[NTOPICS];
    #pragma unroll
    for (int k = 0; k < NTOPICS; k++) creg[k] = g_c[b * NTOPICS + k];

    float* orow = out + (size_t)b * N_COLS + v0;
    #pragma unroll
    for (int vv = 0; vv < VT; vv += 2) {
        int vc = v0 + vv;
        if (vc >= N_COLS) break;
        float2 a = make_float2(0.f, 0.f);
        #pragma unroll
        for (int k = 0; k < NTOPICS; k++) {
            float2 e = *(const float2*)&eb[(rb + k) * EBS + vv];
            a.x += creg[k] * e.x;
            a.y += creg[k] * e.y;
        }
        *(float2*)(orow + vv) = a;   // N_COLS even -> pair fully valid
    }
}

// ---------------------------------------------------------------------------
// kernel_launch
// ---------------------------------------------------------------------------
extern "C" void kernel_launch(void* const* d_in, const int* in_sizes, int n_in,
                              void* d_out, int out_size) {
    const float* theta = nullptr;
    const float* W     = nullptr;
    const float* E     = nullptr;
    const int*   tix   = nullptr;
    for (int i = 0; i < n_in; i++) {
        switch (in_sizes[i]) {
            case 12800:    theta = (const float*)d_in[i]; break;
            case 51200000: W     = (const float*)d_in[i]; break;
            case 512000:   E     = (const float*)d_in[i]; break;
            case 256:      tix   = (const int*)d_in[i];   break;
            default: break;
        }
    }
    float* out = (float*)d_out;

    static int attr_set = 0;
    if (!attr_set) {
        cudaFuncSetAttribute(kgemm, cudaFuncAttributeMaxDynamicSharedMemorySize, GEMM_SMEM);
        cudaFuncSetAttribute(k3_out, cudaFuncAttributeMaxDynamicSharedMemorySize, K3_SMEM);
        attr_set = 1;
    }

    k0_index<<<1, 256>>>(tix);
    prepE<<<(M_PAD * 128) / 256, 256>>>(E);

    dim3 gg(M_PAD / CTA_M, NSTRIP);             // (2, 391) — x fast: B L2 reuse
    kgemm<<<gg, 256, GEMM_SMEM>>>(W);

    k2r<<<M_ROWS, 256>>>();
    k2b_coeff<<<BATCH * NTOPICS / 256, 256>>>(theta);
    k3_out<<<NPART, 256, K3_SMEM>>>(out);       // 782 blocks, one part each
}

// round 17
// speedup vs baseline: 1.0670x; 1.0670x over previous
#include <cuda_runtime.h>
#include <cuda_fp16.h>
#include <math.h>
#include <stdint.h>

// Problem dims
#define TSLICES 10
#define NTOPICS 50
#define M_ROWS  500
#define M_PAD   512
#define N_COLS  50000
#define N_PAD   50048          // 391 strips of 128
#define K_DIM   1024
#define BATCH   256

#define NSTRIP  391
#define CTA_M   256
#define CTA_N   128
#define KSTEP   64
#define NSTAGE  (K_DIM / KSTEP)   // 16
#define NPART   (2 * NSTRIP)      // 782 parts of 64 cols per row

// ---------------------------------------------------------------------------
// Scratch (device globals).  g_eh holds fp16 exp(L - mloc[row,part]).
// ---------------------------------------------------------------------------
__device__ __half g_eh[(size_t)M_ROWS * N_COLS];             // 50 MB
__device__ float g_rowmax[M_ROWS];
__device__ float g_rowsum[M_ROWS];
__device__ float g_c[BATCH * NTOPICS];
__device__ int   g_tidx[BATCH];
__device__ int   g_order[BATCH];                             // batches sorted by t
__device__ float g_pmax[(size_t)M_PAD * NPART];
__device__ float g_psum[(size_t)M_PAD * NPART];

__device__ __align__(16) __half g_Wh[(size_t)N_PAD * K_DIM]; // 102.5 MB
__device__ __align__(16) __half g_Wl[(size_t)N_PAD * K_DIM]; // 102.5 MB
__device__ __align__(16) __half g_Eh[(size_t)M_PAD * K_DIM]; // 1 MB
__device__ __align__(16) __half g_El[(size_t)M_PAD * K_DIM]; // 1 MB

// ---------------------------------------------------------------------------
// PTX helpers (base-target sm_80/90 instructions only)
// ---------------------------------------------------------------------------
__device__ __forceinline__ uint32_t s2u(const void* p) {
    uint32_t a;
    asm("{ .reg .u64 t; cvta.to.shared.u64 t, %1; cvt.u32.u64 %0, t; }" : "=r"(a) : "l"(p));
    return a;
}
__device__ __forceinline__ void cpasync16(uint32_t saddr, const void* gaddr) {
    asm volatile("cp.async.cg.shared.global [%0], [%1], 16;" :: "r"(saddr), "l"(gaddr) : "memory");
}
#define CP_COMMIT() asm volatile("cp.async.commit_group;" ::: "memory")
#define CP_WAIT(n)  asm volatile("cp.async.wait_group %0;" :: "n"(n) : "memory")

__device__ __forceinline__ void ldsm_x4(uint32_t* r, uint32_t a) {
    asm volatile("ldmatrix.sync.aligned.m8n8.x4.shared.b16 {%0,%1,%2,%3}, [%4];"
                 : "=r"(r[0]), "=r"(r[1]), "=r"(r[2]), "=r"(r[3]) : "r"(a));
}
__device__ __forceinline__ void mma16816(float* c, const uint32_t* a, const uint32_t* b) {
    asm volatile("mma.sync.aligned.m16n8k16.row.col.f32.f16.f16.f32 "
                 "{%0,%1,%2,%3}, {%4,%5,%6,%7}, {%8,%9}, {%0,%1,%2,%3};"
                 : "+f"(c[0]), "+f"(c[1]), "+f"(c[2]), "+f"(c[3])
                 : "r"(a[0]), "r"(a[1]), "r"(a[2]), "r"(a[3]), "r"(b[0]), "r"(b[1]));
}
// streaming 16B store (evict-first: these bytes are consumed a kernel later)
__device__ __forceinline__ void stcs16(void* p, uint4 v) {
    asm volatile("st.global.cs.v4.b32 [%0], {%1,%2,%3,%4};"
                 :: "l"(p), "r"(v.x), "r"(v.y), "r"(v.z), "r"(v.w) : "memory");
}
#define SWZ(o) ((o) ^ (((o) >> 3) & 0x70))

// ---------------------------------------------------------------------------
// k0: normalize time_index (int64 vs int32 runtime detect) + counting sort
// ---------------------------------------------------------------------------
__global__ void k0_index(const int* __restrict__ tix_words) {
    __shared__ int s_nonzero;
    __shared__ int tval[BATCH];
    int t = threadIdx.x;
    if (t == 0) s_nonzero = 0;
    __syncthreads();
    if ((t & 1) && tix_words[t] != 0) atomicOr(&s_nonzero, 1);
    __syncthreads();
    int v = (s_nonzero == 0) ? tix_words[2 * t] : tix_words[t];
    g_tidx[t] = v;
    tval[t] = v;
    __syncthreads();
    if (t == 0) {
        int cnt[TSLICES], off[TSLICES];
        #pragma unroll
        for (int s = 0; s < TSLICES; s++) cnt[s] = 0;
        for (int i = 0; i < BATCH; i++) cnt[tval[i]]++;
        int a = 0;
        #pragma unroll
        for (int s = 0; s < TSLICES; s++) { off[s] = a; a += cnt[s]; }
        for (int i = 0; i < BATCH; i++) g_order[off[tval[i]]++] = i;
    }
}

// ---------------------------------------------------------------------------
// fp16 hi/lo split helper: 8 floats -> 4+4 packed words
// ---------------------------------------------------------------------------
__device__ __forceinline__ void split8(const float* x, uint32_t* hw, uint32_t* lw) {
    #pragma unroll
    for (int i = 0; i < 4; i++) {
        __half h0 = __float2half_rn(x[2*i]);
        __half l0 = __float2half_rn(x[2*i]   - __half2float(h0));
        __half h1 = __float2half_rn(x[2*i+1]);
        __half l1 = __float2half_rn(x[2*i+1] - __half2float(h1));
        hw[i] = (uint32_t)__half_as_ushort(h0) | ((uint32_t)__half_as_ushort(h1) << 16);
        lw[i] = (uint32_t)__half_as_ushort(l0) | ((uint32_t)__half_as_ushort(l1) << 16);
    }
}

// ---------------------------------------------------------------------------
// prep: fused W + E split kernel.
// Blocks [0, EBLK): E rows (M_PAD x 1024, 64 threads/row, 16 elems/thread)
// Blocks [EBLK, ..): W rows (N_PAD x 1024, same shape)
// Reads via __ldg (64B/thread), writes via st.global.cs (streaming: the data
// is consumed by the NEXT kernel from DRAM; caching the 205MB only evicts L2).
// ---------------------------------------------------------------------------
#define EBLK ((M_PAD * 64) / 256)                 // 128 blocks for E
#define WBLK ((N_PAD * 64) / 256)                 // 12512 blocks for W
#define PREP_GRID (EBLK + WBLK)

__global__ __launch_bounds__(256) void prep(const float* __restrict__ W,
                                            const float* __restrict__ E) {
    const bool isE = (blockIdx.x < EBLK);
    int idx = (isE ? blockIdx.x : blockIdx.x - EBLK) * 256 + threadIdx.x;
    int row = idx >> 6;                    // row index
    int g   = (idx & 63) * 16;             // first of 16 k-elements
    const float* src   = isE ? E : W;
    const int    rows  = isE ? M_ROWS : N_COLS;
    __half* dh = isE ? g_Eh : g_Wh;
    __half* dl = isE ? g_El : g_Wl;

    float x[16];
    if (row < rows) {
        const float4* p = (const float4*)(src + (size_t)row * K_DIM + g);
        #pragma unroll
        for (int q = 0; q < 4; q++) {
            float4 v = __ldg(p + q);
            x[4*q+0] = v.x; x[4*q+1] = v.y; x[4*q+2] = v.z; x[4*q+3] = v.w;
        }
    } else {
        #pragma unroll
        for (int i = 0; i < 16; i++) x[i] = 0.0f;
    }
    uint32_t hw[8], lw[8];
    split8(x,     hw,     lw);
    split8(x + 8, hw + 4, lw + 4);
    size_t d = (size_t)row * K_DIM + g;    // element offset; /8 -> uint4 index
    stcs16((uint4*)(dh + d),     make_uint4(hw[0], hw[1], hw[2], hw[3]));
    stcs16((uint4*)(dh + d) + 1, make_uint4(hw[4], hw[5], hw[6], hw[7]));
    stcs16((uint4*)(dl + d),     make_uint4(lw[0], lw[1], lw[2], lw[3]));
    stcs16((uint4*)(dl + d) + 1, make_uint4(lw[4], lw[5], lw[6], lw[7]));
}

// ---------------------------------------------------------------------------
// kgemm: HMMA GEMM, fp16 hi/lo 3-product split — R9/R12/R15 mainloop verbatim
// (measured best: ~391-395us, tensor ~65%; believed near the fp32-acc HMMA
// ceiling at 2 warps/SMSP).
// Epilogue: per-(row, 64col part) local max (quad shfl), fp16 exp store
// (max -> 1.0, underflow impossible), partial sums of the SAME fp16 values.
// Smem/stage: Ah 32K | Al 32K | Bh 16K | Bl 16K = 96K; x2 stages = 192K.
// ---------------------------------------------------------------------------
#define ST_STRIDE 98304
#define AH_OFF 0
#define AL_OFF 32768
#define BH_OFF 65536
#define BL_OFF 81920
#define GEMM_SMEM (2 * ST_STRIDE)

__device__ __forceinline__ void issue_stage(uint32_t sb, int buf, int s,
                                            int m0, int n0, int tid) {
    const int k0 = s * KSTEP;
    uint32_t base = sb + buf * ST_STRIDE;
    // A tiles: 256 rows x 128B (hi+lo)
    #pragma unroll
    for (int i = 0; i < 8; i++) {
        int cid = tid + i * 256;
        int row = cid >> 3, c = cid & 7;
        uint32_t sw = SWZ((uint32_t)(row * 128 + c * 16));
        cpasync16(base + AH_OFF + sw, g_Eh + (size_t)(m0 + row) * K_DIM + k0 + c * 8);
        cpasync16(base + AL_OFF + sw, g_El + (size_t)(m0 + row) * K_DIM + k0 + c * 8);
    }
    // B tiles: 128 rows x 128B (hi+lo); padded to N_PAD, no guard
    #pragma unroll
    for (int i = 0; i < 4; i++) {
        int cid = tid + i * 256;
        int row = cid >> 3, c = cid & 7;
        uint32_t sw = SWZ((uint32_t)(row * 128 + c * 16));
        cpasync16(base + BH_OFF + sw, g_Wh + (size_t)(n0 + row) * K_DIM + k0 + c * 8);
        cpasync16(base + BL_OFF + sw, g_Wl + (size_t)(n0 + row) * K_DIM + k0 + c * 8);
    }
}

__global__ __launch_bounds__(256, 1) void kgemm() {
    extern __shared__ char smem[];
    const uint32_t sb = s2u(smem);
    const int tid  = threadIdx.x;
    const int lane = tid & 31;
    const int wid  = tid >> 5;
    const int wm   = (wid >> 1) * 64;   // warp M offset: 0,64,128,192
    const int wn   = (wid & 1) * 64;    // warp N offset: 0,64
    const int m0   = blockIdx.x * CTA_M;   // x fast -> B L2 reuse across M-tiles
    const int n0   = blockIdx.y * CTA_N;

    float acc[4][8][4];
    #pragma unroll
    for (int i = 0; i < 4; i++)
        #pragma unroll
        for (int j = 0; j < 8; j++)
            #pragma unroll
            for (int q = 0; q < 4; q++) acc[i][j][q] = 0.0f;

    // A ldsm_x4 (16x16): lanes 0-15 -> rows, lanes 16-31 -> +16B col
    const int arow = wm + (lane & 15);
    const int acol = (lane >> 4) << 4;
    // B paired ldsm_x4 loads fragments (2jp, 2jp+1)
    const int brow = wn + (lane & 7) + ((lane >> 4) << 3);
    const int bcol = ((lane >> 3) & 1) << 4;

    issue_stage(sb, 0, 0, m0, n0, tid);
    CP_COMMIT();

    for (int s = 0; s < NSTAGE; s++) {
        const int buf = s & 1;
        if (s + 1 < NSTAGE) {
            issue_stage(sb, buf ^ 1, s + 1, m0, n0, tid);
            CP_COMMIT();
            CP_WAIT(1);
        } else {
            CP_WAIT(0);
        }
        __syncthreads();

        const uint32_t tb = sb + buf * ST_STRIDE;
        #pragma unroll
        for (int kk = 0; kk < 4; kk++) {
            const int kb = kk * 32;
            uint32_t ah[4][4], al[4][4], bh[4][4], bl[4][4];
            #pragma unroll
            for (int i = 0; i < 4; i++) {
                uint32_t off = (uint32_t)((arow + i * 16) * 128 + kb + acol);
                ldsm_x4(ah[i], tb + AH_OFF + SWZ(off));
            }
            #pragma unroll
            for (int jp = 0; jp < 4; jp++) {
                uint32_t off = (uint32_t)((brow + jp * 16) * 128 + kb + bcol);
                ldsm_x4(bh[jp], tb + BH_OFF + SWZ(off));
            }
            #pragma unroll
            for (int i = 0; i < 4; i++) {
                uint32_t off = (uint32_t)((arow + i * 16) * 128 + kb + acol);
                ldsm_x4(al[i], tb + AL_OFF + SWZ(off));
            }
            #pragma unroll
            for (int jp = 0; jp < 4; jp++) {
                uint32_t off = (uint32_t)((brow + jp * 16) * 128 + kb + bcol);
                ldsm_x4(bl[jp], tb + BL_OFF + SWZ(off));
            }
            #pragma unroll
            for (int i = 0; i < 4; i++)
                #pragma unroll
                for (int j = 0; j < 8; j++)
                    mma16816(acc[i][j], ah[i], &bh[j >> 1][(j & 1) * 2]);
            #pragma unroll
            for (int i = 0; i < 4; i++)
                #pragma unroll
                for (int j = 0; j < 8; j++)
                    mma16816(acc[i][j], al[i], &bh[j >> 1][(j & 1) * 2]);
            #pragma unroll
            for (int i = 0; i < 4; i++)
                #pragma unroll
                for (int j = 0; j < 8; j++)
                    mma16816(acc[i][j], ah[i], &bl[j >> 1][(j & 1) * 2]);
        }
        __syncthreads();
    }

    // ---- Epilogue: per-(row, part) local max, fp16 store, partial sums ----
    const int erow  = m0 + wm + (lane >> 2);
    const int ecol0 = n0 + wn + 2 * (lane & 3);
    const int part  = blockIdx.y * 2 + (wn >> 6);
    #pragma unroll
    for (int i = 0; i < 4; i++) {
        float m0l = -1e30f, m1l = -1e30f;
        #pragma unroll
        for (int j = 0; j < 8; j++) {
            int cc = ecol0 + j * 8;
            if (cc < N_COLS) {
                m0l = fmaxf(m0l, fmaxf(acc[i][j][0], acc[i][j][1]));
                m1l = fmaxf(m1l, fmaxf(acc[i][j][2], acc[i][j][3]));
            }
        }
        m0l = fmaxf(m0l, __shfl_xor_sync(0xFFFFFFFF, m0l, 1));
        m0l = fmaxf(m0l, __shfl_xor_sync(0xFFFFFFFF, m0l, 2));
        m1l = fmaxf(m1l, __shfl_xor_sync(0xFFFFFFFF, m1l, 1));
        m1l = fmaxf(m1l, __shfl_xor_sync(0xFFFFFFFF, m1l, 2));

        float sl0 = 0.0f, sl1 = 0.0f;
        #pragma unroll
        for (int j = 0; j < 8; j++) {
            int cc = ecol0 + j * 8;
            if (cc >= N_COLS) continue;
            __half h0 = __float2half_rn(__expf(acc[i][j][0] - m0l));
            __half h1 = __float2half_rn(__expf(acc[i][j][1] - m0l));
            __half h2 = __float2half_rn(__expf(acc[i][j][2] - m1l));
            __half h3 = __float2half_rn(__expf(acc[i][j][3] - m1l));
            sl0 += __half2float(h0) + __half2float(h1);
            sl1 += __half2float(h2) + __half2float(h3);
            uint32_t p01 = (uint32_t)__half_as_ushort(h0) | ((uint32_t)__half_as_ushort(h1) << 16);
            uint32_t p23 = (uint32_t)__half_as_ushort(h2) | ((uint32_t)__half_as_ushort(h3) << 16);
            int r0 = erow + i * 16;
            if (r0 < M_ROWS)
                *(uint32_t*)(g_eh + (size_t)r0 * N_COLS + cc) = p01;
            int r1 = r0 + 8;
            if (r1 < M_ROWS)
                *(uint32_t*)(g_eh + (size_t)r1 * N_COLS + cc) = p23;
        }
        sl0 += __shfl_xor_sync(0xFFFFFFFF, sl0, 1);
        sl0 += __shfl_xor_sync(0xFFFFFFFF, sl0, 2);
        sl1 += __shfl_xor_sync(0xFFFFFFFF, sl1, 1);
        sl1 += __shfl_xor_sync(0xFFFFFFFF, sl1, 2);
        if ((lane & 3) == 0) {
            int row0 = erow + i * 16;
            g_pmax[(size_t)row0 * NPART + part] = m0l;
            g_psum[(size_t)row0 * NPART + part] = sl0;
            g_pmax[(size_t)(row0 + 8) * NPART + part] = m1l;
            g_psum[(size_t)(row0 + 8) * NPART + part] = sl1;
        }
    }
}

// ---------------------------------------------------------------------------
// k2r: merge NPART partials per row -> rowmax + rescaled rowsum
// ---------------------------------------------------------------------------
__global__ __launch_bounds__(256) void k2r() {
    const int r = blockIdx.x;
    const float* pm = g_pmax + (size_t)r * NPART;
    const float* ps = g_psum + (size_t)r * NPART;
    __shared__ float red[256];
    const int t = threadIdx.x;

    float m = -1e30f;
    for (int i = t; i < NPART; i += 256) m = fmaxf(m, pm[i]);
    red[t] = m;
    __syncthreads();
    for (int s = 128; s > 0; s >>= 1) {
        if (t < s) red[t] = fmaxf(red[t], red[t + s]);
        __syncthreads();
    }
    m = red[0];
    __syncthreads();

    float sum = 0.0f;
    for (int i = t; i < NPART; i += 256) sum += ps[i] * __expf(pm[i] - m);
    red[t] = sum;
    __syncthreads();
    for (int s = 128; s > 0; s >>= 1) {
        if (t < s) red[t] += red[t + s];
        __syncthreads();
    }
    if (t == 0) { g_rowmax[r] = m; g_rowsum[r] = red[0]; }
}

// ---------------------------------------------------------------------------
// k2b: c[b,k] = theta[b,k] / S[t_b*50+k]
// ---------------------------------------------------------------------------
__global__ void k2b_coeff(const float* __restrict__ theta) {
    int i = blockIdx.x * 256 + threadIdx.x;
    int b = i / NTOPICS, k = i - b * NTOPICS;
    g_c[i] = theta[i] / g_rowsum[g_tidx[b] * NTOPICS + k];
}

// ---------------------------------------------------------------------------
// k3: out[b,v] = sum_k c[b,k] * exp(L - M_r); stored fp16 values rescaled by
// sc[r] = exp(pm[r][part] - M_r) during smem staging. One 64-col part per
// block (782 blocks). Time-sorted batches -> lanes share t -> broadcast.
// ---------------------------------------------------------------------------
#define VT  64
#define EBS 66
#define K3_SMEM ((M_ROWS * EBS + M_ROWS) * 4)   // 134 KB

__global__ __launch_bounds__(256) void k3_out(float* __restrict__ out) {
    extern __shared__ float sm[];
    float* eb = sm;                   // [500][66]
    float* sc = sm + M_ROWS * EBS;    // [500] per-row rescale
    const int part = blockIdx.x;
    const int v0   = part * VT;
    const int tid  = threadIdx.x;

    for (int r = tid; r < M_ROWS; r += 256)
        sc[r] = __expf(g_pmax[(size_t)r * NPART + part] - g_rowmax[r]);
    __syncthreads();

    for (int i = tid; i < M_ROWS * 32; i += 256) {
        int r = i >> 5, p = i & 31;
        int vc = v0 + 2 * p;
        float x0 = 0.f, x1 = 0.f;
        if (vc + 1 < N_COLS) {
            uint32_t w = *(const uint32_t*)(g_eh + (size_t)r * N_COLS + vc);
            float f = sc[r];
            x0 = __half2float(__ushort_as_half((unsigned short)(w & 0xFFFF))) * f;
            x1 = __half2float(__ushort_as_half((unsigned short)(w >> 16))) * f;
        }
        eb[r * EBS + 2 * p]     = x0;
        eb[r * EBS + 2 * p + 1] = x1;
    }
    __syncthreads();

    const int b  = g_order[tid];
    const int rb = g_tidx[b] * NTOPICS;
    float creg[NTOPICS];
    #pragma unroll
    for (int k = 0; k < NTOPICS; k++) creg[k] = g_c[b * NTOPICS + k];

    float* orow = out + (size_t)b * N_COLS + v0;
    #pragma unroll
    for (int vv = 0; vv < VT; vv += 2) {
        int vc = v0 + vv;
        if (vc >= N_COLS) break;
        float2 a = make_float2(0.f, 0.f);
        #pragma unroll
        for (int k = 0; k < NTOPICS; k++) {
            float2 e = *(const float2*)&eb[(rb + k) * EBS + vv];
            a.x += creg[k] * e.x;
            a.y += creg[k] * e.y;
        }
        *(float2*)(orow + vv) = a;   // N_COLS even -> pair fully valid
    }
}

// ---------------------------------------------------------------------------
// kernel_launch
// ---------------------------------------------------------------------------
extern "C" void kernel_launch(void* const* d_in, const int* in_sizes, int n_in,
                              void* d_out, int out_size) {
    const float* theta = nullptr;
    const float* W     = nullptr;
    const float* E     = nullptr;
    const int*   tix   = nullptr;
    for (int i = 0; i < n_in; i++) {
        switch (in_sizes[i]) {
            case 12800:    theta = (const float*)d_in[i]; break;
            case 51200000: W     = (const float*)d_in[i]; break;
            case 512000:   E     = (const float*)d_in[i]; break;
            case 256:      tix   = (const int*)d_in[i];   break;
            default: break;
        }
    }
    float* out = (float*)d_out;

    static int attr_set = 0;
    if (!attr_set) {
        cudaFuncSetAttribute(kgemm, cudaFuncAttributeMaxDynamicSharedMemorySize, GEMM_SMEM);
        cudaFuncSetAttribute(k3_out, cudaFuncAttributeMaxDynamicSharedMemorySize, K3_SMEM);
        attr_set = 1;
    }

    k0_index<<<1, 256>>>(tix);
    prep<<<PREP_GRID, 256>>>(W, E);             // fused W+E split, streaming stores

    dim3 gg(M_PAD / CTA_M, NSTRIP);             // (2, 391) — x fast: B L2 reuse
    kgemm<<<gg, 256, GEMM_SMEM>>>();

    k2r<<<M_ROWS, 256>>>();
    k2b_coeff<<<BATCH * NTOPICS / 256, 256>>>(theta);
    k3_out<<<NPART, 256, K3_SMEM>>>(out);       // 782 blocks, one part each
}